// round 1
// baseline (speedup 1.0000x reference)
#include <cuda_runtime.h>

#define N_NODES 50000
#define N_EDGES 1600000
#define DIM 128
#define N_HEADS 8

// ---------------- scratch (static device globals: no alloc allowed) ----------
__device__ float g_Q[(size_t)N_NODES * DIM];
__device__ float g_K[(size_t)N_NODES * DIM];
__device__ float g_V[(size_t)N_NODES * DIM];
__device__ float g_Eh[(size_t)N_EDGES * DIM];   // 819 MB
__device__ float g_Z[(size_t)N_NODES * N_HEADS];
__device__ int   g_idx64;

// ---------------- edge_index dtype detection (int64 vs int32) ----------------
// JAX with x64 disabled silently downgrades the declared int64 edge_index to
// int32. Detect on device: valid int64 indices lie in [0, N_NODES); int32 data
// reinterpreted as int64 glues the next index into the high 32 bits -> huge.
__global__ void detect_idx_kernel(const void* idx) {
    const long long* p = (const long long*)idx;
    int is64 = 1;
    for (int i = 0; i < 64; i++) {
        long long v = p[i];
        if (v < 0 || v >= N_NODES) { is64 = 0; break; }
    }
    g_idx64 = is64;
}

// ---------------- SGEMM: C[M x 128] = A[M x 128] * W[128 x 128] --------------
// BM=64, BN=128 (full), BK=16; 256 threads; each thread computes 8x4 outputs.
#define BM 64
#define BK 16

__global__ __launch_bounds__(256)
void sgemm128_kernel(const float* __restrict__ A, const float* __restrict__ W,
                     float* __restrict__ C, int M) {
    __shared__ float As[BK][BM + 1];   // +1 pad: kills 4-way STS conflicts
    __shared__ float Ws[BK][DIM];

    const int tid = threadIdx.x;
    const int tx = tid & 31;          // N direction: cols tx*4 .. tx*4+3
    const int ty = tid >> 5;          // M direction: rows ty*8 .. ty*8+7
    const int m0 = blockIdx.x * BM;

    float acc[8][4];
#pragma unroll
    for (int i = 0; i < 8; i++)
#pragma unroll
        for (int j = 0; j < 4; j++) acc[i][j] = 0.0f;

    for (int k0 = 0; k0 < DIM; k0 += BK) {
        // load A tile (64 x 16), store transposed into As
        {
            const int r = tid >> 2;            // 0..63
            const int c = (tid & 3) * 4;       // 0,4,8,12
            const int gr = m0 + r;
            float4 a = make_float4(0.f, 0.f, 0.f, 0.f);
            if (gr < M) a = *(const float4*)(A + (size_t)gr * DIM + k0 + c);
            As[c + 0][r] = a.x;
            As[c + 1][r] = a.y;
            As[c + 2][r] = a.z;
            As[c + 3][r] = a.w;
        }
        // load W tile (16 x 128)
        {
            const int cw = (tid & 31) * 4;
            const int rw = tid >> 5;           // 0..7 (+8 for second half)
            *(float4*)&Ws[rw][cw]     = *(const float4*)(W + (size_t)(k0 + rw) * DIM + cw);
            *(float4*)&Ws[rw + 8][cw] = *(const float4*)(W + (size_t)(k0 + rw + 8) * DIM + cw);
        }
        __syncthreads();

#pragma unroll
        for (int kk = 0; kk < BK; kk++) {
            float a[8];
#pragma unroll
            for (int i = 0; i < 8; i++) a[i] = As[kk][ty * 8 + i];
            const float4 wv = *(const float4*)&Ws[kk][tx * 4];
            const float w0 = wv.x, w1 = wv.y, w2 = wv.z, w3 = wv.w;
#pragma unroll
            for (int i = 0; i < 8; i++) {
                acc[i][0] = fmaf(a[i], w0, acc[i][0]);
                acc[i][1] = fmaf(a[i], w1, acc[i][1]);
                acc[i][2] = fmaf(a[i], w2, acc[i][2]);
                acc[i][3] = fmaf(a[i], w3, acc[i][3]);
            }
        }
        __syncthreads();
    }

#pragma unroll
    for (int i = 0; i < 8; i++) {
        const int gr = m0 + ty * 8 + i;
        if (gr < M) {
            *(float4*)(C + (size_t)gr * DIM + tx * 4) =
                make_float4(acc[i][0], acc[i][1], acc[i][2], acc[i][3]);
        }
    }
}

// ---------------- edge attention: score + scatter-add -----------------------
// One warp per edge. Lane l owns dims 4l..4l+3 (head = l/4).
__global__ __launch_bounds__(256)
void edge_attn_kernel(const float* __restrict__ Eh,
                      const float* __restrict__ Q,
                      const float* __restrict__ K,
                      const float* __restrict__ V,
                      const void* __restrict__ eidx,
                      float* __restrict__ out,    // wV accumulator (d_out)
                      float* __restrict__ Z) {
    const int warp = (blockIdx.x * blockDim.x + threadIdx.x) >> 5;
    const int lane = threadIdx.x & 31;
    if (warp >= N_EDGES) return;
    const int e = warp;

    int src, dst;
    if (g_idx64) {
        const long long* p = (const long long*)eidx;
        src = (int)p[e];
        dst = (int)p[(size_t)N_EDGES + e];
    } else {
        const int* p = (const int*)eidx;
        src = p[e];
        dst = p[N_EDGES + e];
    }

    const float4 eh = ((const float4*)(Eh + (size_t)e   * DIM))[lane];
    const float4 k4 = ((const float4*)(K  + (size_t)src * DIM))[lane];
    const float4 q4 = ((const float4*)(Q  + (size_t)dst * DIM))[lane];

    float s = eh.x * k4.x * q4.x + eh.y * k4.y * q4.y +
              eh.z * k4.z * q4.z + eh.w * k4.w * q4.w;
    // reduce across the 4 lanes of this head
    s += __shfl_xor_sync(0xffffffffu, s, 1);
    s += __shfl_xor_sync(0xffffffffu, s, 2);
    s *= 0.25f;                                   // 1/sqrt(16)
    s = expf(fminf(fmaxf(s, -5.0f), 5.0f));

    const float4 v4 = ((const float4*)(V + (size_t)src * DIM))[lane];
    float* o = out + (size_t)dst * DIM + lane * 4;
    atomicAdd(o + 0, v4.x * s);
    atomicAdd(o + 1, v4.y * s);
    atomicAdd(o + 2, v4.z * s);
    atomicAdd(o + 3, v4.w * s);
    if ((lane & 3) == 0) atomicAdd(&Z[(size_t)dst * N_HEADS + (lane >> 2)], s);
}

// ---------------- final normalize: out /= (Z + 1e-6) -------------------------
__global__ __launch_bounds__(256)
void normalize_kernel(float* __restrict__ out, const float* __restrict__ Z) {
    const int i = blockIdx.x * blockDim.x + threadIdx.x;
    if (i >= N_NODES * DIM) return;
    const int n = i >> 7;
    const int d = i & 127;
    out[i] = out[i] / (Z[(size_t)n * N_HEADS + (d >> 4)] + 1e-6f);
}

// ---------------- launch ------------------------------------------------------
extern "C" void kernel_launch(void* const* d_in, const int* in_sizes, int n_in,
                              void* d_out, int out_size) {
    const float* h   = (const float*)d_in[0];
    const float* ea  = (const float*)d_in[1];
    const float* WQ  = (const float*)d_in[2];
    const float* WK  = (const float*)d_in[3];
    const float* WV  = (const float*)d_in[4];
    const float* WE  = (const float*)d_in[5];
    const void*  eix = d_in[6];
    float* out = (float*)d_out;

    void *qp, *kp, *vp, *ehp, *zp;
    cudaGetSymbolAddress(&qp,  g_Q);
    cudaGetSymbolAddress(&kp,  g_K);
    cudaGetSymbolAddress(&vp,  g_V);
    cudaGetSymbolAddress(&ehp, g_Eh);
    cudaGetSymbolAddress(&zp,  g_Z);

    cudaMemsetAsync(d_out, 0, (size_t)out_size * sizeof(float));
    cudaMemsetAsync(zp, 0, (size_t)N_NODES * N_HEADS * sizeof(float));

    detect_idx_kernel<<<1, 1>>>(eix);

    const int gridN = (N_NODES + BM - 1) / BM;
    sgemm128_kernel<<<gridN, 256>>>(h, WQ, (float*)qp, N_NODES);
    sgemm128_kernel<<<gridN, 256>>>(h, WK, (float*)kp, N_NODES);
    sgemm128_kernel<<<gridN, 256>>>(h, WV, (float*)vp, N_NODES);

    const int gridE = (N_EDGES + BM - 1) / BM;
    sgemm128_kernel<<<gridE, 256>>>(ea, WE, (float*)ehp, N_EDGES);

    // one warp per edge, 8 warps per block
    const int blocksE = (N_EDGES + 7) / 8;
    edge_attn_kernel<<<blocksE, 256>>>((const float*)ehp, (const float*)qp,
                                       (const float*)kp, (const float*)vp,
                                       eix, out, (float*)zp);

    normalize_kernel<<<(N_NODES * DIM + 255) / 256, 256>>>(out, (float*)zp);
}

// round 2
// speedup vs baseline: 1.3843x; 1.3843x over previous
#include <cuda_runtime.h>
#include <cstdint>

#define N_NODES 50000
#define N_EDGES 1600000
#define DIM 128
#define NH 8
#define TILE_E 128
#define PAD 132          // padded row stride (words) for SMEM tiles

// ---------------- scratch (static device globals: no alloc allowed) ----------
__device__ float g_Q[(size_t)N_NODES * DIM];
__device__ float g_K[(size_t)N_NODES * DIM];
__device__ float g_V[(size_t)N_NODES * DIM];
__device__ float g_Z[(size_t)N_NODES * NH];
__device__ int   g_idx64;

// ---------------- edge_index dtype detection (int64 vs int32) ----------------
__global__ void detect_idx_kernel(const void* idx) {
    const long long* p = (const long long*)idx;
    int is64 = 1;
    for (int i = 0; i < 64; i++) {
        long long v = p[i];
        if (v < 0 || v >= N_NODES) { is64 = 0; break; }
    }
    g_idx64 = is64;
}

// ---------------- SGEMM for node projections (fp32, unchanged) ---------------
#define BM 64
#define BK 16

__global__ __launch_bounds__(256)
void sgemm128_kernel(const float* __restrict__ A, const float* __restrict__ W,
                     float* __restrict__ C, int M) {
    __shared__ float As[BK][BM + 1];
    __shared__ float Ws[BK][DIM];

    const int tid = threadIdx.x;
    const int tx = tid & 31;
    const int ty = tid >> 5;
    const int m0 = blockIdx.x * BM;

    float acc[8][4];
#pragma unroll
    for (int i = 0; i < 8; i++)
#pragma unroll
        for (int j = 0; j < 4; j++) acc[i][j] = 0.0f;

    for (int k0 = 0; k0 < DIM; k0 += BK) {
        {
            const int r = tid >> 2;
            const int c = (tid & 3) * 4;
            const int gr = m0 + r;
            float4 a = make_float4(0.f, 0.f, 0.f, 0.f);
            if (gr < M) a = *(const float4*)(A + (size_t)gr * DIM + k0 + c);
            As[c + 0][r] = a.x;
            As[c + 1][r] = a.y;
            As[c + 2][r] = a.z;
            As[c + 3][r] = a.w;
        }
        {
            const int cw = (tid & 31) * 4;
            const int rw = tid >> 5;
            *(float4*)&Ws[rw][cw]     = *(const float4*)(W + (size_t)(k0 + rw) * DIM + cw);
            *(float4*)&Ws[rw + 8][cw] = *(const float4*)(W + (size_t)(k0 + rw + 8) * DIM + cw);
        }
        __syncthreads();

#pragma unroll
        for (int kk = 0; kk < BK; kk++) {
            float a[8];
#pragma unroll
            for (int i = 0; i < 8; i++) a[i] = As[kk][ty * 8 + i];
            const float4 wv = *(const float4*)&Ws[kk][tx * 4];
#pragma unroll
            for (int i = 0; i < 8; i++) {
                acc[i][0] = fmaf(a[i], wv.x, acc[i][0]);
                acc[i][1] = fmaf(a[i], wv.y, acc[i][1]);
                acc[i][2] = fmaf(a[i], wv.z, acc[i][2]);
                acc[i][3] = fmaf(a[i], wv.w, acc[i][3]);
            }
        }
        __syncthreads();
    }

#pragma unroll
    for (int i = 0; i < 8; i++) {
        const int gr = m0 + ty * 8 + i;
        if (gr < M) {
            *(float4*)(C + (size_t)gr * DIM + tx * 4) =
                make_float4(acc[i][0], acc[i][1], acc[i][2], acc[i][3]);
        }
    }
}

// ---------------- tf32 helpers -----------------------------------------------
__device__ __forceinline__ uint32_t f2tf(float f) {
    uint32_t u;
    asm("cvt.rna.tf32.f32 %0, %1;" : "=r"(u) : "f"(f));
    return u;
}

__device__ __forceinline__ void mma_tf32(float* d, const uint32_t* a, const uint32_t* b) {
    asm volatile(
        "mma.sync.aligned.m16n8k8.row.col.f32.tf32.tf32.f32 "
        "{%0,%1,%2,%3}, {%4,%5,%6,%7}, {%8,%9}, {%0,%1,%2,%3};"
        : "+f"(d[0]), "+f"(d[1]), "+f"(d[2]), "+f"(d[3])
        : "r"(a[0]), "r"(a[1]), "r"(a[2]), "r"(a[3]),
          "r"(b[0]), "r"(b[1]));
}

// ---------------- fused edge kernel -------------------------------------------
// Per block: 128 edges. Phase 1: Eh = ea_tile @ WE via tf32 mma.sync (Eh in SMEM
// only — never hits HBM). Phase 2: score = exp(clip(sum K*Q*Eh /4)), scatter
// V[src]*score and score into out/Z with atomics.
// SMEM: As (ea tile, tf32) 128x132, WEs (tf32) 128x132, Eh (fp32) 128x132.
__global__ __launch_bounds__(256, 1)
void fused_edge_kernel(const float* __restrict__ ea,
                       const float* __restrict__ WE,
                       const float* __restrict__ Q,
                       const float* __restrict__ K,
                       const float* __restrict__ V,
                       const void* __restrict__ eidx,
                       float* __restrict__ out,
                       float* __restrict__ Z) {
    extern __shared__ float smem[];
    uint32_t* Asu = (uint32_t*)smem;                  // 128*PAD
    uint32_t* Wsu = (uint32_t*)(smem + 128 * PAD);    // 128*PAD
    float*    Eh  = smem + 2 * 128 * PAD;             // 128*PAD

    const int tid  = threadIdx.x;
    const int lane = tid & 31;
    const int w    = tid >> 5;
    const int e0   = blockIdx.x * TILE_E;

    // ---- load WE and ea tile into SMEM, converting to tf32 ----
#pragma unroll
    for (int i = 0; i < 16; i++) {
        const int fidx = tid + 256 * i;        // 0..4095 float4 slots
        const int r  = fidx >> 5;
        const int c4 = (fidx & 31) << 2;
        float4 wv = *(const float4*)(WE + (size_t)r * DIM + c4);
        uint4 wu = make_uint4(f2tf(wv.x), f2tf(wv.y), f2tf(wv.z), f2tf(wv.w));
        *(uint4*)&Wsu[r * PAD + c4] = wu;

        float4 av = *(const float4*)(ea + (size_t)(e0 + r) * DIM + c4);
        uint4 au = make_uint4(f2tf(av.x), f2tf(av.y), f2tf(av.z), f2tf(av.w));
        *(uint4*)&Asu[r * PAD + c4] = au;
    }
    __syncthreads();

    // ---- GEMM: warp computes 64 edges x 32 cols ----
    const int mb = (w & 1) * 64;        // edge (M) block
    const int nb = (w >> 1) * 32;       // col  (N) block
    const int g  = lane >> 2;
    const int cc = lane & 3;

    float acc[4][4][4];
#pragma unroll
    for (int mt = 0; mt < 4; mt++)
#pragma unroll
        for (int nt = 0; nt < 4; nt++)
#pragma unroll
            for (int q = 0; q < 4; q++) acc[mt][nt][q] = 0.0f;

#pragma unroll
    for (int ks = 0; ks < 16; ks++) {
        const int kc = 8 * ks + cc;
        uint32_t a[4][4];
#pragma unroll
        for (int mt = 0; mt < 4; mt++) {
            const int r = mb + 16 * mt + g;
            a[mt][0] = Asu[r * PAD + kc];
            a[mt][1] = Asu[(r + 8) * PAD + kc];
            a[mt][2] = Asu[r * PAD + kc + 4];
            a[mt][3] = Asu[(r + 8) * PAD + kc + 4];
        }
        uint32_t b[4][2];
#pragma unroll
        for (int nt = 0; nt < 4; nt++) {
            const int n = nb + 8 * nt + g;
            b[nt][0] = Wsu[kc * PAD + n];
            b[nt][1] = Wsu[(kc + 4) * PAD + n];
        }
#pragma unroll
        for (int mt = 0; mt < 4; mt++)
#pragma unroll
            for (int nt = 0; nt < 4; nt++)
                mma_tf32(acc[mt][nt], a[mt], b[nt]);
    }

    // ---- write Eh tile to SMEM ----
#pragma unroll
    for (int mt = 0; mt < 4; mt++) {
#pragma unroll
        for (int nt = 0; nt < 4; nt++) {
            const int r   = mb + 16 * mt + g;
            const int col = nb + 8 * nt + 2 * cc;
            *(float2*)&Eh[r * PAD + col]       = make_float2(acc[mt][nt][0], acc[mt][nt][1]);
            *(float2*)&Eh[(r + 8) * PAD + col] = make_float2(acc[mt][nt][2], acc[mt][nt][3]);
        }
    }
    __syncthreads();

    // ---- score + scatter: warp w handles edges 16w..16w+15, 4 at a time ----
    const bool idx64 = (g_idx64 != 0);
#pragma unroll 1
    for (int b0 = 0; b0 < 16; b0 += 4) {
        int src[4], dst[4];
        float4 ehv[4], kv[4], qv[4];
#pragma unroll
        for (int j = 0; j < 4; j++) {
            const int el = w * 16 + b0 + j;
            const int e  = e0 + el;
            if (idx64) {
                const long long* p = (const long long*)eidx;
                src[j] = (int)__ldg(p + e);
                dst[j] = (int)__ldg(p + (size_t)N_EDGES + e);
            } else {
                const int* p = (const int*)eidx;
                src[j] = __ldg(p + e);
                dst[j] = __ldg(p + N_EDGES + e);
            }
            ehv[j] = *(const float4*)&Eh[el * PAD + 4 * lane];
            kv[j]  = __ldg((const float4*)(K + (size_t)src[j] * DIM) + lane);
            qv[j]  = __ldg((const float4*)(Q + (size_t)dst[j] * DIM) + lane);
        }
#pragma unroll
        for (int j = 0; j < 4; j++) {
            float s = ehv[j].x * kv[j].x * qv[j].x + ehv[j].y * kv[j].y * qv[j].y +
                      ehv[j].z * kv[j].z * qv[j].z + ehv[j].w * kv[j].w * qv[j].w;
            s += __shfl_xor_sync(0xffffffffu, s, 1);
            s += __shfl_xor_sync(0xffffffffu, s, 2);
            s *= 0.25f;
            s = expf(fminf(fmaxf(s, -5.0f), 5.0f));

            const float4 vv = __ldg((const float4*)(V + (size_t)src[j] * DIM) + lane);
            float* o = out + (size_t)dst[j] * DIM + lane * 4;
            atomicAdd(o + 0, vv.x * s);
            atomicAdd(o + 1, vv.y * s);
            atomicAdd(o + 2, vv.z * s);
            atomicAdd(o + 3, vv.w * s);
            if ((lane & 3) == 0)
                atomicAdd(&Z[(size_t)dst[j] * NH + (lane >> 2)], s);
        }
    }
}

// ---------------- final normalize ---------------------------------------------
__global__ __launch_bounds__(256)
void normalize_kernel(float* __restrict__ out, const float* __restrict__ Z) {
    const int i = blockIdx.x * blockDim.x + threadIdx.x;
    if (i >= N_NODES * DIM) return;
    const int n = i >> 7;
    const int d = i & 127;
    out[i] = out[i] / (Z[(size_t)n * NH + (d >> 4)] + 1e-6f);
}

// ---------------- launch --------------------------------------------------------
extern "C" void kernel_launch(void* const* d_in, const int* in_sizes, int n_in,
                              void* d_out, int out_size) {
    const float* h   = (const float*)d_in[0];
    const float* ea  = (const float*)d_in[1];
    const float* WQ  = (const float*)d_in[2];
    const float* WK  = (const float*)d_in[3];
    const float* WV  = (const float*)d_in[4];
    const float* WE  = (const float*)d_in[5];
    const void*  eix = d_in[6];
    float* out = (float*)d_out;

    void *qp, *kp, *vp, *zp;
    cudaGetSymbolAddress(&qp, g_Q);
    cudaGetSymbolAddress(&kp, g_K);
    cudaGetSymbolAddress(&vp, g_V);
    cudaGetSymbolAddress(&zp, g_Z);

    cudaMemsetAsync(d_out, 0, (size_t)out_size * sizeof(float));
    cudaMemsetAsync(zp, 0, (size_t)N_NODES * NH * sizeof(float));

    detect_idx_kernel<<<1, 1>>>(eix);

    const int gridN = (N_NODES + BM - 1) / BM;
    sgemm128_kernel<<<gridN, 256>>>(h, WQ, (float*)qp, N_NODES);
    sgemm128_kernel<<<gridN, 256>>>(h, WK, (float*)kp, N_NODES);
    sgemm128_kernel<<<gridN, 256>>>(h, WV, (float*)vp, N_NODES);

    const int smem_bytes = 3 * 128 * PAD * sizeof(float);   // 202752
    cudaFuncSetAttribute(fused_edge_kernel,
                         cudaFuncAttributeMaxDynamicSharedMemorySize, smem_bytes);
    fused_edge_kernel<<<N_EDGES / TILE_E, 256, smem_bytes>>>(
        ea, WE, (const float*)qp, (const float*)kp, (const float*)vp,
        eix, out, (float*)zp);

    normalize_kernel<<<(N_NODES * DIM + 255) / 256, 256>>>(out, (float*)zp);
}

// round 3
// speedup vs baseline: 1.4185x; 1.0247x over previous
#include <cuda_runtime.h>
#include <cstdint>

#define N_NODES 50000
#define N_EDGES 1600000
#define DIM 128
#define NH 8
#define TILE_E 128
#define PAD 132          // padded row stride (words) for SMEM tiles

// ---------------- scratch (static device globals: no alloc allowed) ----------
__device__ float g_Q[(size_t)N_NODES * DIM];
__device__ float g_K[(size_t)N_NODES * DIM];
__device__ float g_V[(size_t)N_NODES * DIM];
__device__ int   g_cnt[N_NODES];
__device__ int   g_base[N_NODES + 1];
__device__ int   g_psrc[N_EDGES];
__device__ float g_pscore[(size_t)N_EDGES * NH];   // 51 MB
__device__ int   g_idx64;

// ---------------- edge_index dtype detection (int64 vs int32) ----------------
__global__ void detect_idx_kernel(const void* idx) {
    const long long* p = (const long long*)idx;
    int is64 = 1;
    for (int i = 0; i < 64; i++) {
        long long v = p[i];
        if (v < 0 || v >= N_NODES) { is64 = 0; break; }
    }
    g_idx64 = is64;
}

// ---------------- histogram of dst --------------------------------------------
__global__ __launch_bounds__(256)
void hist_kernel(const void* __restrict__ eidx, int* __restrict__ cnt) {
    const int i = blockIdx.x * blockDim.x + threadIdx.x;
    if (i >= N_EDGES) return;
    int dst;
    if (g_idx64) dst = (int)((const long long*)eidx)[(size_t)N_EDGES + i];
    else         dst = ((const int*)eidx)[N_EDGES + i];
    atomicAdd(&cnt[dst], 1);
}

// ---------------- single-block exclusive scan (1024 threads) ------------------
__global__ __launch_bounds__(1024)
void scan_kernel(const int* __restrict__ cnt, int* __restrict__ base) {
    __shared__ int wsum[32];
    const int tid = threadIdx.x;
    const int lane = tid & 31, wid = tid >> 5;
    const int CH = (N_NODES + 1023) / 1024;   // 49
    const int start = tid * CH;

    int s = 0;
    for (int i = 0; i < CH; i++) {
        const int idx = start + i;
        if (idx < N_NODES) s += cnt[idx];
    }
    int v = s;
#pragma unroll
    for (int d = 1; d < 32; d <<= 1) {
        int n = __shfl_up_sync(0xffffffffu, v, d);
        if (lane >= d) v += n;
    }
    if (lane == 31) wsum[wid] = v;
    __syncthreads();
    if (wid == 0) {
        int wv = wsum[lane];
#pragma unroll
        for (int d = 1; d < 32; d <<= 1) {
            int n = __shfl_up_sync(0xffffffffu, wv, d);
            if (lane >= d) wv += n;
        }
        wsum[lane] = wv;
    }
    __syncthreads();
    int run = v - s + (wid > 0 ? wsum[wid - 1] : 0);
    for (int i = 0; i < CH; i++) {
        const int idx = start + i;
        if (idx < N_NODES) { base[idx] = run; run += cnt[idx]; }
    }
    if (tid == 1023) base[N_NODES] = run;
}

// ---------------- node projections: 3 GEMMs in one launch (gridDim.y) ---------
#define BM 64
#define BK 16

__global__ __launch_bounds__(256)
void sgemm3_kernel(const float* __restrict__ A,
                   const float* __restrict__ WQ, const float* __restrict__ WK,
                   const float* __restrict__ WV,
                   float* __restrict__ Q, float* __restrict__ K,
                   float* __restrict__ V, int M) {
    const float* W = (blockIdx.y == 0) ? WQ : (blockIdx.y == 1) ? WK : WV;
    float*       C = (blockIdx.y == 0) ? Q  : (blockIdx.y == 1) ? K  : V;

    __shared__ float As[BK][BM + 1];
    __shared__ float Ws[BK][DIM];

    const int tid = threadIdx.x;
    const int tx = tid & 31;
    const int ty = tid >> 5;
    const int m0 = blockIdx.x * BM;

    float acc[8][4];
#pragma unroll
    for (int i = 0; i < 8; i++)
#pragma unroll
        for (int j = 0; j < 4; j++) acc[i][j] = 0.0f;

    for (int k0 = 0; k0 < DIM; k0 += BK) {
        {
            const int r = tid >> 2;
            const int c = (tid & 3) * 4;
            const int gr = m0 + r;
            float4 a = make_float4(0.f, 0.f, 0.f, 0.f);
            if (gr < M) a = *(const float4*)(A + (size_t)gr * DIM + k0 + c);
            As[c + 0][r] = a.x;
            As[c + 1][r] = a.y;
            As[c + 2][r] = a.z;
            As[c + 3][r] = a.w;
        }
        {
            const int cw = (tid & 31) * 4;
            const int rw = tid >> 5;
            *(float4*)&Ws[rw][cw]     = *(const float4*)(W + (size_t)(k0 + rw) * DIM + cw);
            *(float4*)&Ws[rw + 8][cw] = *(const float4*)(W + (size_t)(k0 + rw + 8) * DIM + cw);
        }
        __syncthreads();

#pragma unroll
        for (int kk = 0; kk < BK; kk++) {
            float a[8];
#pragma unroll
            for (int i = 0; i < 8; i++) a[i] = As[kk][ty * 8 + i];
            const float4 wv = *(const float4*)&Ws[kk][tx * 4];
#pragma unroll
            for (int i = 0; i < 8; i++) {
                acc[i][0] = fmaf(a[i], wv.x, acc[i][0]);
                acc[i][1] = fmaf(a[i], wv.y, acc[i][1]);
                acc[i][2] = fmaf(a[i], wv.z, acc[i][2]);
                acc[i][3] = fmaf(a[i], wv.w, acc[i][3]);
            }
        }
        __syncthreads();
    }

#pragma unroll
    for (int i = 0; i < 8; i++) {
        const int gr = m0 + ty * 8 + i;
        if (gr < M) {
            *(float4*)(C + (size_t)gr * DIM + tx * 4) =
                make_float4(acc[i][0], acc[i][1], acc[i][2], acc[i][3]);
        }
    }
}

// ---------------- tf32 helpers -----------------------------------------------
__device__ __forceinline__ uint32_t f2tf(float f) {
    uint32_t u;
    asm("cvt.rna.tf32.f32 %0, %1;" : "=r"(u) : "f"(f));
    return u;
}

__device__ __forceinline__ void mma_tf32(float* d, const uint32_t* a, const uint32_t* b) {
    asm volatile(
        "mma.sync.aligned.m16n8k8.row.col.f32.tf32.tf32.f32 "
        "{%0,%1,%2,%3}, {%4,%5,%6,%7}, {%8,%9}, {%0,%1,%2,%3};"
        : "+f"(d[0]), "+f"(d[1]), "+f"(d[2]), "+f"(d[3])
        : "r"(a[0]), "r"(a[1]), "r"(a[2]), "r"(a[3]),
          "r"(b[0]), "r"(b[1]));
}

// ---------------- fused edge kernel: GEMM + score + CSR slot write ------------
// 512 threads, 1 CTA/SM. Phase 1: Eh = ea_tile @ WE (tf32 mma, SMEM-resident).
// Phase 2: s = exp(clip(sum K*Q*Eh / 4)); claim CSR slot with ONE atomic per
// edge; write (src, 8 scores) to permuted arrays. No output atomics.
__global__ __launch_bounds__(512, 1)
void fused_edge_kernel(const float* __restrict__ ea,
                       const float* __restrict__ WE,
                       const float* __restrict__ Q,
                       const float* __restrict__ K,
                       const void* __restrict__ eidx,
                       const int* __restrict__ base,
                       int* __restrict__ cnt,
                       int* __restrict__ psrc,
                       float* __restrict__ pscore) {
    extern __shared__ float smem[];
    uint32_t* Asu = (uint32_t*)smem;                  // 128*PAD
    uint32_t* Wsu = (uint32_t*)(smem + 128 * PAD);    // 128*PAD
    float*    Eh  = smem + 2 * 128 * PAD;             // 128*PAD

    const int tid  = threadIdx.x;
    const int lane = tid & 31;
    const int w    = tid >> 5;                        // 0..15
    const int e0   = blockIdx.x * TILE_E;

    // ---- load WE and ea tile into SMEM, converting to tf32 ----
#pragma unroll
    for (int i = 0; i < 8; i++) {
        const int fidx = tid + 512 * i;               // 0..4095 float4 slots
        const int r  = fidx >> 5;
        const int c4 = (fidx & 31) << 2;
        float4 wv = *(const float4*)(WE + (size_t)r * DIM + c4);
        *(uint4*)&Wsu[r * PAD + c4] =
            make_uint4(f2tf(wv.x), f2tf(wv.y), f2tf(wv.z), f2tf(wv.w));
        float4 av = *(const float4*)(ea + (size_t)(e0 + r) * DIM + c4);
        *(uint4*)&Asu[r * PAD + c4] =
            make_uint4(f2tf(av.x), f2tf(av.y), f2tf(av.z), f2tf(av.w));
    }
    __syncthreads();

    // ---- GEMM: each of 16 warps computes 32 edges x 32 cols ----
    const int mb = (w & 3) * 32;
    const int nb = (w >> 2) * 32;
    const int g  = lane >> 2;
    const int cc = lane & 3;

    float acc[2][4][4];
#pragma unroll
    for (int mt = 0; mt < 2; mt++)
#pragma unroll
        for (int nt = 0; nt < 4; nt++)
#pragma unroll
            for (int q = 0; q < 4; q++) acc[mt][nt][q] = 0.0f;

#pragma unroll
    for (int ks = 0; ks < 16; ks++) {
        const int kc = 8 * ks + cc;
        uint32_t a[2][4];
#pragma unroll
        for (int mt = 0; mt < 2; mt++) {
            const int r = mb + 16 * mt + g;
            a[mt][0] = Asu[r * PAD + kc];
            a[mt][1] = Asu[(r + 8) * PAD + kc];
            a[mt][2] = Asu[r * PAD + kc + 4];
            a[mt][3] = Asu[(r + 8) * PAD + kc + 4];
        }
        uint32_t b[4][2];
#pragma unroll
        for (int nt = 0; nt < 4; nt++) {
            const int n = nb + 8 * nt + g;
            b[nt][0] = Wsu[kc * PAD + n];
            b[nt][1] = Wsu[(kc + 4) * PAD + n];
        }
#pragma unroll
        for (int mt = 0; mt < 2; mt++)
#pragma unroll
            for (int nt = 0; nt < 4; nt++)
                mma_tf32(acc[mt][nt], a[mt], b[nt]);
    }

    // ---- write Eh tile to SMEM ----
#pragma unroll
    for (int mt = 0; mt < 2; mt++) {
#pragma unroll
        for (int nt = 0; nt < 4; nt++) {
            const int r   = mb + 16 * mt + g;
            const int col = nb + 8 * nt + 2 * cc;
            *(float2*)&Eh[r * PAD + col]       = make_float2(acc[mt][nt][0], acc[mt][nt][1]);
            *(float2*)&Eh[(r + 8) * PAD + col] = make_float2(acc[mt][nt][2], acc[mt][nt][3]);
        }
    }
    __syncthreads();

    // ---- score + CSR slot write: warp w handles edges 8w..8w+7 ----
    const bool idx64 = (g_idx64 != 0);
#pragma unroll 1
    for (int b0 = 0; b0 < 8; b0 += 4) {
        int src[4], dst[4];
        float4 ehv[4], kv[4], qv[4];
#pragma unroll
        for (int j = 0; j < 4; j++) {
            const int el = w * 8 + b0 + j;
            const int e  = e0 + el;
            if (idx64) {
                const long long* p = (const long long*)eidx;
                src[j] = (int)__ldg(p + e);
                dst[j] = (int)__ldg(p + (size_t)N_EDGES + e);
            } else {
                const int* p = (const int*)eidx;
                src[j] = __ldg(p + e);
                dst[j] = __ldg(p + N_EDGES + e);
            }
            ehv[j] = *(const float4*)&Eh[el * PAD + 4 * lane];
            kv[j]  = __ldg((const float4*)(K + (size_t)src[j] * DIM) + lane);
            qv[j]  = __ldg((const float4*)(Q + (size_t)dst[j] * DIM) + lane);
        }
#pragma unroll
        for (int j = 0; j < 4; j++) {
            float s = ehv[j].x * kv[j].x * qv[j].x + ehv[j].y * kv[j].y * qv[j].y +
                      ehv[j].z * kv[j].z * qv[j].z + ehv[j].w * kv[j].w * qv[j].w;
            s += __shfl_xor_sync(0xffffffffu, s, 1);
            s += __shfl_xor_sync(0xffffffffu, s, 2);
            s *= 0.25f;
            s = expf(fminf(fmaxf(s, -5.0f), 5.0f));

            int pos = 0;
            if (lane == 0) pos = base[dst[j]] + atomicAdd(&cnt[dst[j]], 1);
            pos = __shfl_sync(0xffffffffu, pos, 0);
            if (lane == 0) psrc[pos] = src[j];
            if ((lane & 3) == 0) pscore[(size_t)pos * NH + (lane >> 2)] = s;
        }
    }
}

// ---------------- gather: one warp per node, register accumulation ------------
__global__ __launch_bounds__(256)
void gather_kernel(const int* __restrict__ base,
                   const int* __restrict__ psrc,
                   const float* __restrict__ pscore,
                   const float* __restrict__ V,
                   float* __restrict__ out) {
    const int node = (blockIdx.x * blockDim.x + threadIdx.x) >> 5;
    const int lane = threadIdx.x & 31;
    if (node >= N_NODES) return;

    const int b = base[node];
    const int e = base[node + 1];

    float4 acc = make_float4(0.f, 0.f, 0.f, 0.f);
    float z = 0.f;
#pragma unroll 2
    for (int j = b; j < e; j++) {
        const int   src = __ldg(psrc + j);
        const float s   = __ldg(pscore + (size_t)j * NH + (lane >> 2));
        const float4 v  = __ldg((const float4*)(V + (size_t)src * DIM) + lane);
        acc.x = fmaf(v.x, s, acc.x);
        acc.y = fmaf(v.y, s, acc.y);
        acc.z = fmaf(v.z, s, acc.z);
        acc.w = fmaf(v.w, s, acc.w);
        z += s;
    }
    const float inv = 1.0f / (z + 1e-6f);
    *(float4*)(out + (size_t)node * DIM + lane * 4) =
        make_float4(acc.x * inv, acc.y * inv, acc.z * inv, acc.w * inv);
}

// ---------------- launch --------------------------------------------------------
extern "C" void kernel_launch(void* const* d_in, const int* in_sizes, int n_in,
                              void* d_out, int out_size) {
    const float* h   = (const float*)d_in[0];
    const float* ea  = (const float*)d_in[1];
    const float* WQ  = (const float*)d_in[2];
    const float* WK  = (const float*)d_in[3];
    const float* WV  = (const float*)d_in[4];
    const float* WE  = (const float*)d_in[5];
    const void*  eix = d_in[6];
    float* out = (float*)d_out;

    void *qp, *kp, *vp, *cntp, *basep, *psrcp, *pscorep;
    cudaGetSymbolAddress(&qp,     g_Q);
    cudaGetSymbolAddress(&kp,     g_K);
    cudaGetSymbolAddress(&vp,     g_V);
    cudaGetSymbolAddress(&cntp,   g_cnt);
    cudaGetSymbolAddress(&basep,  g_base);
    cudaGetSymbolAddress(&psrcp,  g_psrc);
    cudaGetSymbolAddress(&pscorep, g_pscore);

    detect_idx_kernel<<<1, 1>>>(eix);

    // CSR build
    cudaMemsetAsync(cntp, 0, N_NODES * sizeof(int));
    hist_kernel<<<(N_EDGES + 255) / 256, 256>>>(eix, (int*)cntp);
    scan_kernel<<<1, 1024>>>((const int*)cntp, (int*)basep);
    cudaMemsetAsync(cntp, 0, N_NODES * sizeof(int));

    // node projections (3 GEMMs in one launch)
    dim3 gN((N_NODES + BM - 1) / BM, 3);
    sgemm3_kernel<<<gN, 256>>>(h, WQ, WK, WV, (float*)qp, (float*)kp, (float*)vp,
                               N_NODES);

    // fused edge GEMM + score + slot write
    const int smem_bytes = 3 * 128 * PAD * sizeof(float);   // 202752
    cudaFuncSetAttribute(fused_edge_kernel,
                         cudaFuncAttributeMaxDynamicSharedMemorySize, smem_bytes);
    fused_edge_kernel<<<N_EDGES / TILE_E, 512, smem_bytes>>>(
        ea, WE, (const float*)qp, (const float*)kp, eix,
        (const int*)basep, (int*)cntp, (int*)psrcp, (float*)pscorep);

    // gather + normalize (one warp per node)
    gather_kernel<<<(N_NODES * 32 + 255) / 256, 256>>>(
        (const int*)basep, (const int*)psrcp, (const float*)pscorep,
        (const float*)vp, out);
}

// round 4
// speedup vs baseline: 1.8296x; 1.2898x over previous
#include <cuda_runtime.h>
#include <cstdint>

#define N_NODES 50000
#define N_EDGES 1600000
#define DIM 128
#define NH 8
#define TILE_E 64
#define PAD 132          // padded row stride (words) for SMEM tiles

// ---------------- scratch (static device globals: no alloc allowed) ----------
__device__ float g_Q[(size_t)N_NODES * DIM];
__device__ float g_K[(size_t)N_NODES * DIM];
__device__ float g_V[(size_t)N_NODES * DIM];
__device__ int   g_cnt[N_NODES];
__device__ int   g_base[N_NODES + 1];
__device__ int   g_src32[N_EDGES];
__device__ int   g_dst32[N_EDGES];
__device__ int   g_pos[N_EDGES];
__device__ int   g_psrc[N_EDGES];
__device__ float g_pscore[(size_t)N_EDGES * NH];   // 51 MB
__device__ int   g_idx64;

// ---------------- edge_index dtype detection (int64 vs int32) ----------------
__global__ void detect_idx_kernel(const void* idx) {
    const long long* p = (const long long*)idx;
    int is64 = 1;
    for (int i = 0; i < 64; i++) {
        long long v = p[i];
        if (v < 0 || v >= N_NODES) { is64 = 0; break; }
    }
    g_idx64 = is64;
}

// ---------------- histogram of dst --------------------------------------------
__global__ __launch_bounds__(256)
void hist_kernel(const void* __restrict__ eidx, int* __restrict__ cnt) {
    const int i = blockIdx.x * blockDim.x + threadIdx.x;
    if (i >= N_EDGES) return;
    int dst;
    if (g_idx64) dst = (int)((const long long*)eidx)[(size_t)N_EDGES + i];
    else         dst = ((const int*)eidx)[N_EDGES + i];
    atomicAdd(&cnt[dst], 1);
}

// ---------------- single-block exclusive scan (1024 threads) ------------------
__global__ __launch_bounds__(1024)
void scan_kernel(const int* __restrict__ cnt, int* __restrict__ base) {
    __shared__ int wsum[32];
    const int tid = threadIdx.x;
    const int lane = tid & 31, wid = tid >> 5;
    const int CH = (N_NODES + 1023) / 1024;   // 49
    const int start = tid * CH;

    int s = 0;
    for (int i = 0; i < CH; i++) {
        const int idx = start + i;
        if (idx < N_NODES) s += cnt[idx];
    }
    int v = s;
#pragma unroll
    for (int d = 1; d < 32; d <<= 1) {
        int n = __shfl_up_sync(0xffffffffu, v, d);
        if (lane >= d) v += n;
    }
    if (lane == 31) wsum[wid] = v;
    __syncthreads();
    if (wid == 0) {
        int wv = wsum[lane];
#pragma unroll
        for (int d = 1; d < 32; d <<= 1) {
            int n = __shfl_up_sync(0xffffffffu, wv, d);
            if (lane >= d) wv += n;
        }
        wsum[lane] = wv;
    }
    __syncthreads();
    int run = v - s + (wid > 0 ? wsum[wid - 1] : 0);
    for (int i = 0; i < CH; i++) {
        const int idx = start + i;
        if (idx < N_NODES) { base[idx] = run; run += cnt[idx]; }
    }
    if (tid == 1023) base[N_NODES] = run;
}

// ---------------- convert: int32 indices + CSR slot assignment ----------------
__global__ __launch_bounds__(256)
void convert_kernel(const void* __restrict__ eidx,
                    const int* __restrict__ base, int* __restrict__ cnt,
                    int* __restrict__ src32, int* __restrict__ dst32,
                    int* __restrict__ pos, int* __restrict__ psrc) {
    const int i = blockIdx.x * blockDim.x + threadIdx.x;
    if (i >= N_EDGES) return;
    int s, d;
    if (g_idx64) {
        const long long* p = (const long long*)eidx;
        s = (int)p[i];
        d = (int)p[(size_t)N_EDGES + i];
    } else {
        const int* p = (const int*)eidx;
        s = p[i];
        d = p[N_EDGES + i];
    }
    src32[i] = s;
    dst32[i] = d;
    const int pp = base[d] + atomicAdd(&cnt[d], 1);
    pos[i] = pp;
    psrc[pp] = s;
}

// ---------------- node projections: 3 GEMMs in one launch (gridDim.y) ---------
#define BM 64
#define BK 16

__global__ __launch_bounds__(256)
void sgemm3_kernel(const float* __restrict__ A,
                   const float* __restrict__ WQ, const float* __restrict__ WK,
                   const float* __restrict__ WV,
                   float* __restrict__ Q, float* __restrict__ K,
                   float* __restrict__ V, int M) {
    const float* W = (blockIdx.y == 0) ? WQ : (blockIdx.y == 1) ? WK : WV;
    float*       C = (blockIdx.y == 0) ? Q  : (blockIdx.y == 1) ? K  : V;

    __shared__ float As[BK][BM + 1];
    __shared__ float Ws[BK][DIM];

    const int tid = threadIdx.x;
    const int tx = tid & 31;
    const int ty = tid >> 5;
    const int m0 = blockIdx.x * BM;

    float acc[8][4];
#pragma unroll
    for (int i = 0; i < 8; i++)
#pragma unroll
        for (int j = 0; j < 4; j++) acc[i][j] = 0.0f;

    for (int k0 = 0; k0 < DIM; k0 += BK) {
        {
            const int r = tid >> 2;
            const int c = (tid & 3) * 4;
            const int gr = m0 + r;
            float4 a = make_float4(0.f, 0.f, 0.f, 0.f);
            if (gr < M) a = *(const float4*)(A + (size_t)gr * DIM + k0 + c);
            As[c + 0][r] = a.x;
            As[c + 1][r] = a.y;
            As[c + 2][r] = a.z;
            As[c + 3][r] = a.w;
        }
        {
            const int cw = (tid & 31) * 4;
            const int rw = tid >> 5;
            *(float4*)&Ws[rw][cw]     = *(const float4*)(W + (size_t)(k0 + rw) * DIM + cw);
            *(float4*)&Ws[rw + 8][cw] = *(const float4*)(W + (size_t)(k0 + rw + 8) * DIM + cw);
        }
        __syncthreads();

#pragma unroll
        for (int kk = 0; kk < BK; kk++) {
            float a[8];
#pragma unroll
            for (int i = 0; i < 8; i++) a[i] = As[kk][ty * 8 + i];
            const float4 wv = *(const float4*)&Ws[kk][tx * 4];
#pragma unroll
            for (int i = 0; i < 8; i++) {
                acc[i][0] = fmaf(a[i], wv.x, acc[i][0]);
                acc[i][1] = fmaf(a[i], wv.y, acc[i][1]);
                acc[i][2] = fmaf(a[i], wv.z, acc[i][2]);
                acc[i][3] = fmaf(a[i], wv.w, acc[i][3]);
            }
        }
        __syncthreads();
    }

#pragma unroll
    for (int i = 0; i < 8; i++) {
        const int gr = m0 + ty * 8 + i;
        if (gr < M) {
            *(float4*)(C + (size_t)gr * DIM + tx * 4) =
                make_float4(acc[i][0], acc[i][1], acc[i][2], acc[i][3]);
        }
    }
}

// ---------------- tf32 helpers -----------------------------------------------
__device__ __forceinline__ uint32_t f2tf(float f) {
    uint32_t u;
    asm("cvt.rna.tf32.f32 %0, %1;" : "=r"(u) : "f"(f));
    return u;
}

__device__ __forceinline__ void mma_tf32(float* d, const uint32_t* a, const uint32_t* b) {
    asm volatile(
        "mma.sync.aligned.m16n8k8.row.col.f32.tf32.tf32.f32 "
        "{%0,%1,%2,%3}, {%4,%5,%6,%7}, {%8,%9}, {%0,%1,%2,%3};"
        : "+f"(d[0]), "+f"(d[1]), "+f"(d[2]), "+f"(d[3])
        : "r"(a[0]), "r"(a[1]), "r"(a[2]), "r"(a[3]),
          "r"(b[0]), "r"(b[1]));
}

// ---------------- fused edge kernel: GEMM + score + CSR slot write ------------
// 64 edges/block, 256 threads, 2 CTAs/SM (SMEM 101 KB) -> cross-CTA phase
// overlap. Phase 1: Eh = ea_tile @ WE (tf32 mma), Eh overwrites the ea tile.
// Phase 2: s = exp(clip(sum K*Q*Eh / 4)); scores written to precomputed CSR
// slots. No atomics, no branches on idx dtype.
__global__ __launch_bounds__(256, 2)
void fused_edge_kernel(const float* __restrict__ ea,
                       const float* __restrict__ WE,
                       const float* __restrict__ Q,
                       const float* __restrict__ K,
                       const int* __restrict__ src32,
                       const int* __restrict__ dst32,
                       const int* __restrict__ pos,
                       float* __restrict__ pscore) {
    extern __shared__ float smem[];
    uint32_t* Asu = (uint32_t*)smem;                       // 64*PAD (reused as Eh)
    uint32_t* Wsu = (uint32_t*)(smem + TILE_E * PAD);      // 128*PAD

    const int tid  = threadIdx.x;
    const int lane = tid & 31;
    const int w    = tid >> 5;                             // 0..7
    const int e0   = blockIdx.x * TILE_E;

    // ---- load WE (128x128) and ea tile (64x128) into SMEM as tf32 ----
#pragma unroll
    for (int i = 0; i < 16; i++) {
        const int fidx = tid + 256 * i;        // 0..4095
        const int r  = fidx >> 5;
        const int c4 = (fidx & 31) << 2;
        float4 wv = *(const float4*)(WE + (size_t)r * DIM + c4);
        *(uint4*)&Wsu[r * PAD + c4] =
            make_uint4(f2tf(wv.x), f2tf(wv.y), f2tf(wv.z), f2tf(wv.w));
    }
#pragma unroll
    for (int i = 0; i < 8; i++) {
        const int fidx = tid + 256 * i;        // 0..2047
        const int r  = fidx >> 5;              // 0..63
        const int c4 = (fidx & 31) << 2;
        float4 av = *(const float4*)(ea + (size_t)(e0 + r) * DIM + c4);
        *(uint4*)&Asu[r * PAD + c4] =
            make_uint4(f2tf(av.x), f2tf(av.y), f2tf(av.z), f2tf(av.w));
    }
    __syncthreads();

    // ---- GEMM: 8 warps, each computes 32 edges x 32 cols ----
    const int mb = (w & 1) * 32;
    const int nb = (w >> 1) * 32;
    const int g  = lane >> 2;
    const int cc = lane & 3;

    float acc[2][4][4];
#pragma unroll
    for (int mt = 0; mt < 2; mt++)
#pragma unroll
        for (int nt = 0; nt < 4; nt++)
#pragma unroll
            for (int q = 0; q < 4; q++) acc[mt][nt][q] = 0.0f;

#pragma unroll
    for (int ks = 0; ks < 16; ks++) {
        const int kc = 8 * ks + cc;
        uint32_t a[2][4];
#pragma unroll
        for (int mt = 0; mt < 2; mt++) {
            const int r = mb + 16 * mt + g;
            a[mt][0] = Asu[r * PAD + kc];
            a[mt][1] = Asu[(r + 8) * PAD + kc];
            a[mt][2] = Asu[r * PAD + kc + 4];
            a[mt][3] = Asu[(r + 8) * PAD + kc + 4];
        }
        uint32_t b[4][2];
#pragma unroll
        for (int nt = 0; nt < 4; nt++) {
            const int n = nb + 8 * nt + g;
            b[nt][0] = Wsu[kc * PAD + n];
            b[nt][1] = Wsu[(kc + 4) * PAD + n];
        }
#pragma unroll
        for (int mt = 0; mt < 2; mt++)
#pragma unroll
            for (int nt = 0; nt < 4; nt++)
                mma_tf32(acc[mt][nt], a[mt], b[nt]);
    }
    __syncthreads();   // everyone done READING Asu

    // ---- write Eh tile over the ea tile ----
    float* Eh = smem;   // alias of Asu
#pragma unroll
    for (int mt = 0; mt < 2; mt++) {
#pragma unroll
        for (int nt = 0; nt < 4; nt++) {
            const int r   = mb + 16 * mt + g;
            const int col = nb + 8 * nt + 2 * cc;
            *(float2*)&Eh[r * PAD + col]       = make_float2(acc[mt][nt][0], acc[mt][nt][1]);
            *(float2*)&Eh[(r + 8) * PAD + col] = make_float2(acc[mt][nt][2], acc[mt][nt][3]);
        }
    }
    __syncthreads();

    // ---- score + slot write: warp w handles edges 8w..8w+7, 4 at a time ----
#pragma unroll 1
    for (int b0 = 0; b0 < 8; b0 += 4) {
        int src[4], dst[4], pp[4];
        float4 ehv[4], kv[4], qv[4];
#pragma unroll
        for (int j = 0; j < 4; j++) {
            const int el = w * 8 + b0 + j;
            const int e  = e0 + el;
            src[j] = __ldg(src32 + e);
            dst[j] = __ldg(dst32 + e);
            pp[j]  = __ldg(pos + e);
            ehv[j] = *(const float4*)&Eh[el * PAD + 4 * lane];
            kv[j]  = __ldg((const float4*)(K + (size_t)src[j] * DIM) + lane);
            qv[j]  = __ldg((const float4*)(Q + (size_t)dst[j] * DIM) + lane);
        }
#pragma unroll
        for (int j = 0; j < 4; j++) {
            float s = ehv[j].x * kv[j].x * qv[j].x + ehv[j].y * kv[j].y * qv[j].y +
                      ehv[j].z * kv[j].z * qv[j].z + ehv[j].w * kv[j].w * qv[j].w;
            s += __shfl_xor_sync(0xffffffffu, s, 1);
            s += __shfl_xor_sync(0xffffffffu, s, 2);
            s *= 0.25f;
            s = expf(fminf(fmaxf(s, -5.0f), 5.0f));
            if ((lane & 3) == 0)
                pscore[(size_t)pp[j] * NH + (lane >> 2)] = s;
        }
    }
}

// ---------------- gather: one warp per node, register accumulation ------------
__global__ __launch_bounds__(256)
void gather_kernel(const int* __restrict__ base,
                   const int* __restrict__ psrc,
                   const float* __restrict__ pscore,
                   const float* __restrict__ V,
                   float* __restrict__ out) {
    const int node = (blockIdx.x * blockDim.x + threadIdx.x) >> 5;
    const int lane = threadIdx.x & 31;
    if (node >= N_NODES) return;

    const int b = base[node];
    const int e = base[node + 1];
    const int h = lane >> 2;

    float4 acc = make_float4(0.f, 0.f, 0.f, 0.f);
    float z = 0.f;

    for (int cb = b; cb < e; cb += 32) {
        const int n = min(32, e - cb);
        int mysrc = 0;
        if (cb + lane < e) mysrc = __ldg(psrc + cb + lane);

        int i = 0;
        for (; i + 4 <= n; i += 4) {
#pragma unroll
            for (int u = 0; u < 4; u++) {
                const int src = __shfl_sync(0xffffffffu, mysrc, i + u);
                const float s = __ldg(pscore + (size_t)(cb + i + u) * NH + h);
                const float4 v = __ldg((const float4*)(V + (size_t)src * DIM) + lane);
                acc.x = fmaf(v.x, s, acc.x);
                acc.y = fmaf(v.y, s, acc.y);
                acc.z = fmaf(v.z, s, acc.z);
                acc.w = fmaf(v.w, s, acc.w);
                z += s;
            }
        }
        for (; i < n; i++) {
            const int src = __shfl_sync(0xffffffffu, mysrc, i);
            const float s = __ldg(pscore + (size_t)(cb + i) * NH + h);
            const float4 v = __ldg((const float4*)(V + (size_t)src * DIM) + lane);
            acc.x = fmaf(v.x, s, acc.x);
            acc.y = fmaf(v.y, s, acc.y);
            acc.z = fmaf(v.z, s, acc.z);
            acc.w = fmaf(v.w, s, acc.w);
            z += s;
        }
    }
    const float inv = 1.0f / (z + 1e-6f);
    *(float4*)(out + (size_t)node * DIM + lane * 4) =
        make_float4(acc.x * inv, acc.y * inv, acc.z * inv, acc.w * inv);
}

// ---------------- launch --------------------------------------------------------
extern "C" void kernel_launch(void* const* d_in, const int* in_sizes, int n_in,
                              void* d_out, int out_size) {
    const float* h   = (const float*)d_in[0];
    const float* ea  = (const float*)d_in[1];
    const float* WQ  = (const float*)d_in[2];
    const float* WK  = (const float*)d_in[3];
    const float* WV  = (const float*)d_in[4];
    const float* WE  = (const float*)d_in[5];
    const void*  eix = d_in[6];
    float* out = (float*)d_out;

    void *qp, *kp, *vp, *cntp, *basep, *srcp, *dstp, *posp, *psrcp, *pscorep;
    cudaGetSymbolAddress(&qp,      g_Q);
    cudaGetSymbolAddress(&kp,      g_K);
    cudaGetSymbolAddress(&vp,      g_V);
    cudaGetSymbolAddress(&cntp,    g_cnt);
    cudaGetSymbolAddress(&basep,   g_base);
    cudaGetSymbolAddress(&srcp,    g_src32);
    cudaGetSymbolAddress(&dstp,    g_dst32);
    cudaGetSymbolAddress(&posp,    g_pos);
    cudaGetSymbolAddress(&psrcp,   g_psrc);
    cudaGetSymbolAddress(&pscorep, g_pscore);

    detect_idx_kernel<<<1, 1>>>(eix);

    // CSR build
    cudaMemsetAsync(cntp, 0, N_NODES * sizeof(int));
    hist_kernel<<<(N_EDGES + 255) / 256, 256>>>(eix, (int*)cntp);
    scan_kernel<<<1, 1024>>>((const int*)cntp, (int*)basep);
    cudaMemsetAsync(cntp, 0, N_NODES * sizeof(int));
    convert_kernel<<<(N_EDGES + 255) / 256, 256>>>(
        eix, (const int*)basep, (int*)cntp,
        (int*)srcp, (int*)dstp, (int*)posp, (int*)psrcp);

    // node projections (3 GEMMs in one launch)
    dim3 gN((N_NODES + BM - 1) / BM, 3);
    sgemm3_kernel<<<gN, 256>>>(h, WQ, WK, WV, (float*)qp, (float*)kp, (float*)vp,
                               N_NODES);

    // fused edge GEMM + score + slot write (2 CTAs/SM)
    const int smem_bytes = (TILE_E + 128) * PAD * sizeof(float);   // 101376
    cudaFuncSetAttribute(fused_edge_kernel,
                         cudaFuncAttributeMaxDynamicSharedMemorySize, smem_bytes);
    fused_edge_kernel<<<N_EDGES / TILE_E, 256, smem_bytes>>>(
        ea, WE, (const float*)qp, (const float*)kp,
        (const int*)srcp, (const int*)dstp, (const int*)posp, (float*)pscorep);

    // gather + normalize (one warp per node)
    gather_kernel<<<(N_NODES * 32 + 255) / 256, 256>>>(
        (const int*)basep, (const int*)psrcp, (const float*)pscorep,
        (const float*)vp, out);
}

// round 5
// speedup vs baseline: 1.8597x; 1.0164x over previous
#include <cuda_runtime.h>
#include <cstdint>

#define N_NODES 50000
#define N_EDGES 1600000
#define DIM 128
#define NH 8
#define TILE_E 64
#define PAD 132          // padded row stride (words) for SMEM tiles

// ---------------- scratch (static device globals: no alloc allowed) ----------
__device__ float g_Q[(size_t)N_NODES * DIM];
__device__ float g_K[(size_t)N_NODES * DIM];
__device__ float g_V[(size_t)N_NODES * DIM];
__device__ int   g_cnt[N_NODES];
__device__ int   g_base[N_NODES + 1];
__device__ int   g_psrc[N_EDGES];     // slot -> src node
__device__ int   g_pdst[N_EDGES];     // slot -> dst node
__device__ int   g_pinv[N_EDGES];     // slot -> original edge id
__device__ float g_pscore[(size_t)N_EDGES * NH];   // 51 MB
__device__ int   g_idx64;

// ---------------- edge_index dtype detection (int64 vs int32) ----------------
__global__ void detect_idx_kernel(const void* idx) {
    const long long* p = (const long long*)idx;
    int is64 = 1;
    for (int i = 0; i < 64; i++) {
        long long v = p[i];
        if (v < 0 || v >= N_NODES) { is64 = 0; break; }
    }
    g_idx64 = is64;
}

// ---------------- histogram of dst --------------------------------------------
__global__ __launch_bounds__(256)
void hist_kernel(const void* __restrict__ eidx, int* __restrict__ cnt) {
    const int i = blockIdx.x * blockDim.x + threadIdx.x;
    if (i >= N_EDGES) return;
    int dst;
    if (g_idx64) dst = (int)((const long long*)eidx)[(size_t)N_EDGES + i];
    else         dst = ((const int*)eidx)[N_EDGES + i];
    atomicAdd(&cnt[dst], 1);
}

// ---------------- single-block exclusive scan (1024 threads) ------------------
__global__ __launch_bounds__(1024)
void scan_kernel(const int* __restrict__ cnt, int* __restrict__ base) {
    __shared__ int wsum[32];
    const int tid = threadIdx.x;
    const int lane = tid & 31, wid = tid >> 5;
    const int CH = (N_NODES + 1023) / 1024;   // 49
    const int start = tid * CH;

    int s = 0;
    for (int i = 0; i < CH; i++) {
        const int idx = start + i;
        if (idx < N_NODES) s += cnt[idx];
    }
    int v = s;
#pragma unroll
    for (int d = 1; d < 32; d <<= 1) {
        int n = __shfl_up_sync(0xffffffffu, v, d);
        if (lane >= d) v += n;
    }
    if (lane == 31) wsum[wid] = v;
    __syncthreads();
    if (wid == 0) {
        int wv = wsum[lane];
#pragma unroll
        for (int d = 1; d < 32; d <<= 1) {
            int n = __shfl_up_sync(0xffffffffu, wv, d);
            if (lane >= d) wv += n;
        }
        wsum[lane] = wv;
    }
    __syncthreads();
    int run = v - s + (wid > 0 ? wsum[wid - 1] : 0);
    for (int i = 0; i < CH; i++) {
        const int idx = start + i;
        if (idx < N_NODES) { base[idx] = run; run += cnt[idx]; }
    }
    if (tid == 1023) base[N_NODES] = run;
}

// ---------------- convert: CSR slot assignment + permutation arrays ----------
__global__ __launch_bounds__(256)
void convert_kernel(const void* __restrict__ eidx,
                    const int* __restrict__ base, int* __restrict__ cnt,
                    int* __restrict__ psrc, int* __restrict__ pdst,
                    int* __restrict__ pinv) {
    const int i = blockIdx.x * blockDim.x + threadIdx.x;
    if (i >= N_EDGES) return;
    int s, d;
    if (g_idx64) {
        const long long* p = (const long long*)eidx;
        s = (int)p[i];
        d = (int)p[(size_t)N_EDGES + i];
    } else {
        const int* p = (const int*)eidx;
        s = p[i];
        d = p[N_EDGES + i];
    }
    const int pp = base[d] + atomicAdd(&cnt[d], 1);
    psrc[pp] = s;
    pdst[pp] = d;
    pinv[pp] = i;
}

// ---------------- node projections: 3 GEMMs in one launch (gridDim.y) ---------
#define BM 64
#define BK 16

__global__ __launch_bounds__(256)
void sgemm3_kernel(const float* __restrict__ A,
                   const float* __restrict__ WQ, const float* __restrict__ WK,
                   const float* __restrict__ WV,
                   float* __restrict__ Q, float* __restrict__ K,
                   float* __restrict__ V, int M) {
    const float* W = (blockIdx.y == 0) ? WQ : (blockIdx.y == 1) ? WK : WV;
    float*       C = (blockIdx.y == 0) ? Q  : (blockIdx.y == 1) ? K  : V;

    __shared__ float As[BK][BM + 1];
    __shared__ float Ws[BK][DIM];

    const int tid = threadIdx.x;
    const int tx = tid & 31;
    const int ty = tid >> 5;
    const int m0 = blockIdx.x * BM;

    float acc[8][4];
#pragma unroll
    for (int i = 0; i < 8; i++)
#pragma unroll
        for (int j = 0; j < 4; j++) acc[i][j] = 0.0f;

    for (int k0 = 0; k0 < DIM; k0 += BK) {
        {
            const int r = tid >> 2;
            const int c = (tid & 3) * 4;
            const int gr = m0 + r;
            float4 a = make_float4(0.f, 0.f, 0.f, 0.f);
            if (gr < M) a = *(const float4*)(A + (size_t)gr * DIM + k0 + c);
            As[c + 0][r] = a.x;
            As[c + 1][r] = a.y;
            As[c + 2][r] = a.z;
            As[c + 3][r] = a.w;
        }
        {
            const int cw = (tid & 31) * 4;
            const int rw = tid >> 5;
            *(float4*)&Ws[rw][cw]     = *(const float4*)(W + (size_t)(k0 + rw) * DIM + cw);
            *(float4*)&Ws[rw + 8][cw] = *(const float4*)(W + (size_t)(k0 + rw + 8) * DIM + cw);
        }
        __syncthreads();

#pragma unroll
        for (int kk = 0; kk < BK; kk++) {
            float a[8];
#pragma unroll
            for (int i = 0; i < 8; i++) a[i] = As[kk][ty * 8 + i];
            const float4 wv = *(const float4*)&Ws[kk][tx * 4];
#pragma unroll
            for (int i = 0; i < 8; i++) {
                acc[i][0] = fmaf(a[i], wv.x, acc[i][0]);
                acc[i][1] = fmaf(a[i], wv.y, acc[i][1]);
                acc[i][2] = fmaf(a[i], wv.z, acc[i][2]);
                acc[i][3] = fmaf(a[i], wv.w, acc[i][3]);
            }
        }
        __syncthreads();
    }

#pragma unroll
    for (int i = 0; i < 8; i++) {
        const int gr = m0 + ty * 8 + i;
        if (gr < M) {
            *(float4*)(C + (size_t)gr * DIM + tx * 4) =
                make_float4(acc[i][0], acc[i][1], acc[i][2], acc[i][3]);
        }
    }
}

// ---------------- tf32 helpers -----------------------------------------------
__device__ __forceinline__ uint32_t f2tf(float f) {
    uint32_t u;
    asm("cvt.rna.tf32.f32 %0, %1;" : "=r"(u) : "f"(f));
    return u;
}

__device__ __forceinline__ void mma_tf32(float* d, const uint32_t* a, const uint32_t* b) {
    asm volatile(
        "mma.sync.aligned.m16n8k8.row.col.f32.tf32.tf32.f32 "
        "{%0,%1,%2,%3}, {%4,%5,%6,%7}, {%8,%9}, {%0,%1,%2,%3};"
        : "+f"(d[0]), "+f"(d[1]), "+f"(d[2]), "+f"(d[3])
        : "r"(a[0]), "r"(a[1]), "r"(a[2]), "r"(a[3]),
          "r"(b[0]), "r"(b[1]));
}

// ---------------- fused edge kernel (CSR-ordered slots) -----------------------
// Tiles walk SLOT space (edges sorted by dst). ea rows gathered via pinv
// (one coalesced 512B row per warp-load). Q[dst] gathers hit ~2 distinct rows
// per tile (L2 broadcast). pscore writes are sequential. 2 CTAs/SM.
__global__ __launch_bounds__(256, 2)
void fused_edge_kernel(const float* __restrict__ ea,
                       const float* __restrict__ WE,
                       const float* __restrict__ Q,
                       const float* __restrict__ K,
                       const int* __restrict__ psrc,
                       const int* __restrict__ pdst,
                       const int* __restrict__ pinv,
                       float* __restrict__ pscore) {
    extern __shared__ float smem[];
    uint32_t* Asu = (uint32_t*)smem;                       // 64*PAD (reused as Eh)
    uint32_t* Wsu = (uint32_t*)(smem + TILE_E * PAD);      // 128*PAD

    const int tid  = threadIdx.x;
    const int lane = tid & 31;
    const int w    = tid >> 5;                             // 0..7
    const int e0   = blockIdx.x * TILE_E;

    // pinv for this warp's 8 rows (rows w, w+8, ..., w+56) in lane registers
    int myp = 0;
    if (lane < 8) myp = __ldg(pinv + e0 + w + 8 * lane);

    // ---- load WE (128x128) into SMEM as tf32 ----
#pragma unroll
    for (int i = 0; i < 16; i++) {
        const int fidx = tid + 256 * i;        // 0..4095
        const int r  = fidx >> 5;
        const int c4 = (fidx & 31) << 2;
        float4 wv = *(const float4*)(WE + (size_t)r * DIM + c4);
        *(uint4*)&Wsu[r * PAD + c4] =
            make_uint4(f2tf(wv.x), f2tf(wv.y), f2tf(wv.z), f2tf(wv.w));
    }
    // ---- gather ea rows (64 x 128) by original edge id ----
#pragma unroll
    for (int i = 0; i < 8; i++) {
        const int eid = __shfl_sync(0xffffffffu, myp, i);
        const int r   = w + 8 * i;
        float4 av = *(const float4*)(ea + (size_t)eid * DIM + lane * 4);
        *(uint4*)&Asu[r * PAD + lane * 4] =
            make_uint4(f2tf(av.x), f2tf(av.y), f2tf(av.z), f2tf(av.w));
    }
    __syncthreads();

    // ---- GEMM: 8 warps, each computes 32 slots x 32 cols ----
    const int mb = (w & 1) * 32;
    const int nb = (w >> 1) * 32;
    const int g  = lane >> 2;
    const int cc = lane & 3;

    float acc[2][4][4];
#pragma unroll
    for (int mt = 0; mt < 2; mt++)
#pragma unroll
        for (int nt = 0; nt < 4; nt++)
#pragma unroll
            for (int q = 0; q < 4; q++) acc[mt][nt][q] = 0.0f;

#pragma unroll
    for (int ks = 0; ks < 16; ks++) {
        const int kc = 8 * ks + cc;
        uint32_t a[2][4];
#pragma unroll
        for (int mt = 0; mt < 2; mt++) {
            const int r = mb + 16 * mt + g;
            a[mt][0] = Asu[r * PAD + kc];
            a[mt][1] = Asu[(r + 8) * PAD + kc];
            a[mt][2] = Asu[r * PAD + kc + 4];
            a[mt][3] = Asu[(r + 8) * PAD + kc + 4];
        }
        uint32_t b[4][2];
#pragma unroll
        for (int nt = 0; nt < 4; nt++) {
            const int n = nb + 8 * nt + g;
            b[nt][0] = Wsu[kc * PAD + n];
            b[nt][1] = Wsu[(kc + 4) * PAD + n];
        }
#pragma unroll
        for (int mt = 0; mt < 2; mt++)
#pragma unroll
            for (int nt = 0; nt < 4; nt++)
                mma_tf32(acc[mt][nt], a[mt], b[nt]);
    }
    __syncthreads();   // everyone done READING Asu

    // ---- write Eh tile over the ea tile ----
    float* Eh = smem;   // alias of Asu
#pragma unroll
    for (int mt = 0; mt < 2; mt++) {
#pragma unroll
        for (int nt = 0; nt < 4; nt++) {
            const int r   = mb + 16 * mt + g;
            const int col = nb + 8 * nt + 2 * cc;
            *(float2*)&Eh[r * PAD + col]       = make_float2(acc[mt][nt][0], acc[mt][nt][1]);
            *(float2*)&Eh[(r + 8) * PAD + col] = make_float2(acc[mt][nt][2], acc[mt][nt][3]);
        }
    }
    __syncthreads();

    // ---- score + sequential slot write: warp w handles slots 8w..8w+7 ----
#pragma unroll 1
    for (int b0 = 0; b0 < 8; b0 += 4) {
        int src[4];
        float4 ehv[4], kv[4], qv[4];
#pragma unroll
        for (int j = 0; j < 4; j++) {
            const int el   = w * 8 + b0 + j;
            const int slot = e0 + el;
            src[j] = __ldg(psrc + slot);
            const int dst = __ldg(pdst + slot);
            ehv[j] = *(const float4*)&Eh[el * PAD + 4 * lane];
            kv[j]  = __ldg((const float4*)(K + (size_t)src[j] * DIM) + lane);
            qv[j]  = __ldg((const float4*)(Q + (size_t)dst * DIM) + lane);
        }
#pragma unroll
        for (int j = 0; j < 4; j++) {
            float s = ehv[j].x * kv[j].x * qv[j].x + ehv[j].y * kv[j].y * qv[j].y +
                      ehv[j].z * kv[j].z * qv[j].z + ehv[j].w * kv[j].w * qv[j].w;
            s += __shfl_xor_sync(0xffffffffu, s, 1);
            s += __shfl_xor_sync(0xffffffffu, s, 2);
            s *= 0.25f;
            s = expf(fminf(fmaxf(s, -5.0f), 5.0f));
            if ((lane & 3) == 0)
                pscore[(size_t)(e0 + w * 8 + b0 + j) * NH + (lane >> 2)] = s;
        }
    }
}

// ---------------- gather: one warp per node, register accumulation ------------
__global__ __launch_bounds__(256)
void gather_kernel(const int* __restrict__ base,
                   const int* __restrict__ psrc,
                   const float* __restrict__ pscore,
                   const float* __restrict__ V,
                   float* __restrict__ out) {
    const int node = (blockIdx.x * blockDim.x + threadIdx.x) >> 5;
    const int lane = threadIdx.x & 31;
    if (node >= N_NODES) return;

    const int b = base[node];
    const int e = base[node + 1];
    const int h = lane >> 2;

    float4 acc = make_float4(0.f, 0.f, 0.f, 0.f);
    float z = 0.f;

    for (int cb = b; cb < e; cb += 32) {
        const int n = min(32, e - cb);
        int mysrc = 0;
        if (cb + lane < e) mysrc = __ldg(psrc + cb + lane);

        int i = 0;
        for (; i + 8 <= n; i += 8) {
#pragma unroll
            for (int u = 0; u < 8; u++) {
                const int src = __shfl_sync(0xffffffffu, mysrc, i + u);
                const float s = __ldg(pscore + (size_t)(cb + i + u) * NH + h);
                const float4 v = __ldg((const float4*)(V + (size_t)src * DIM) + lane);
                acc.x = fmaf(v.x, s, acc.x);
                acc.y = fmaf(v.y, s, acc.y);
                acc.z = fmaf(v.z, s, acc.z);
                acc.w = fmaf(v.w, s, acc.w);
                z += s;
            }
        }
        for (; i < n; i++) {
            const int src = __shfl_sync(0xffffffffu, mysrc, i);
            const float s = __ldg(pscore + (size_t)(cb + i) * NH + h);
            const float4 v = __ldg((const float4*)(V + (size_t)src * DIM) + lane);
            acc.x = fmaf(v.x, s, acc.x);
            acc.y = fmaf(v.y, s, acc.y);
            acc.z = fmaf(v.z, s, acc.z);
            acc.w = fmaf(v.w, s, acc.w);
            z += s;
        }
    }
    const float inv = 1.0f / (z + 1e-6f);
    *(float4*)(out + (size_t)node * DIM + lane * 4) =
        make_float4(acc.x * inv, acc.y * inv, acc.z * inv, acc.w * inv);
}

// ---------------- launch --------------------------------------------------------
extern "C" void kernel_launch(void* const* d_in, const int* in_sizes, int n_in,
                              void* d_out, int out_size) {
    const float* h   = (const float*)d_in[0];
    const float* ea  = (const float*)d_in[1];
    const float* WQ  = (const float*)d_in[2];
    const float* WK  = (const float*)d_in[3];
    const float* WV  = (const float*)d_in[4];
    const float* WE  = (const float*)d_in[5];
    const void*  eix = d_in[6];
    float* out = (float*)d_out;

    void *qp, *kp, *vp, *cntp, *basep, *psrcp, *pdstp, *pinvp, *pscorep;
    cudaGetSymbolAddress(&qp,      g_Q);
    cudaGetSymbolAddress(&kp,      g_K);
    cudaGetSymbolAddress(&vp,      g_V);
    cudaGetSymbolAddress(&cntp,    g_cnt);
    cudaGetSymbolAddress(&basep,   g_base);
    cudaGetSymbolAddress(&psrcp,   g_psrc);
    cudaGetSymbolAddress(&pdstp,   g_pdst);
    cudaGetSymbolAddress(&pinvp,   g_pinv);
    cudaGetSymbolAddress(&pscorep, g_pscore);

    detect_idx_kernel<<<1, 1>>>(eix);

    // CSR build
    cudaMemsetAsync(cntp, 0, N_NODES * sizeof(int));
    hist_kernel<<<(N_EDGES + 255) / 256, 256>>>(eix, (int*)cntp);
    scan_kernel<<<1, 1024>>>((const int*)cntp, (int*)basep);
    cudaMemsetAsync(cntp, 0, N_NODES * sizeof(int));
    convert_kernel<<<(N_EDGES + 255) / 256, 256>>>(
        eix, (const int*)basep, (int*)cntp,
        (int*)psrcp, (int*)pdstp, (int*)pinvp);

    // node projections (3 GEMMs in one launch)
    dim3 gN((N_NODES + BM - 1) / BM, 3);
    sgemm3_kernel<<<gN, 256>>>(h, WQ, WK, WV, (float*)qp, (float*)kp, (float*)vp,
                               N_NODES);

    // fused edge GEMM + score (CSR slot order, 2 CTAs/SM)
    const int smem_bytes = (TILE_E + 128) * PAD * sizeof(float);   // 101376
    cudaFuncSetAttribute(fused_edge_kernel,
                         cudaFuncAttributeMaxDynamicSharedMemorySize, smem_bytes);
    fused_edge_kernel<<<N_EDGES / TILE_E, 256, smem_bytes>>>(
        ea, WE, (const float*)qp, (const float*)kp,
        (const int*)psrcp, (const int*)pdstp, (const int*)pinvp,
        (float*)pscorep);

    // gather + normalize (one warp per node)
    gather_kernel<<<(N_NODES * 32 + 255) / 256, 256>>>(
        (const int*)basep, (const int*)psrcp, (const float*)pscorep,
        (const float*)vp, out);
}

// round 7
// speedup vs baseline: 1.9492x; 1.0481x over previous
#include <cuda_runtime.h>
#include <cstdint>

#define N_NODES 50000
#define N_EDGES 1600000
#define DIM 128
#define NH 8
#define TILE_E 64
#define NTILES (N_EDGES / TILE_E)   // 25000
#define NPER 304                    // persistent CTAs (2 per SM x 152 SMs)
#define PAD 132                     // padded row stride (words) for SMEM tiles

// ---------------- scratch (static device globals: no alloc allowed) ----------
__device__ float g_Q[(size_t)N_NODES * DIM];
__device__ float g_K[(size_t)N_NODES * DIM];
__device__ float g_V[(size_t)N_NODES * DIM];
__device__ int   g_cnt[N_NODES];
__device__ int   g_base[N_NODES + 1];
__device__ int   g_psrc[N_EDGES];     // slot -> src node
__device__ int   g_pdst[N_EDGES];     // slot -> dst node
__device__ int   g_pinv[N_EDGES];     // slot -> original edge id
__device__ float g_pscore[(size_t)N_EDGES * NH];   // 51 MB
__device__ int   g_idx64;

// ---------------- edge_index dtype detection (int64 vs int32) ----------------
__global__ void detect_idx_kernel(const void* idx) {
    const long long* p = (const long long*)idx;
    int is64 = 1;
    for (int i = 0; i < 64; i++) {
        long long v = p[i];
        if (v < 0 || v >= N_NODES) { is64 = 0; break; }
    }
    g_idx64 = is64;
}

// ---------------- histogram of dst --------------------------------------------
__global__ __launch_bounds__(256)
void hist_kernel(const void* __restrict__ eidx, int* __restrict__ cnt) {
    const int i = blockIdx.x * blockDim.x + threadIdx.x;
    if (i >= N_EDGES) return;
    int dst;
    if (g_idx64) dst = (int)((const long long*)eidx)[(size_t)N_EDGES + i];
    else         dst = ((const int*)eidx)[N_EDGES + i];
    atomicAdd(&cnt[dst], 1);
}

// ---------------- single-block exclusive scan (1024 threads) ------------------
__global__ __launch_bounds__(1024)
void scan_kernel(const int* __restrict__ cnt, int* __restrict__ base) {
    __shared__ int wsum[32];
    const int tid = threadIdx.x;
    const int lane = tid & 31, wid = tid >> 5;
    const int CH = (N_NODES + 1023) / 1024;   // 49
    const int start = tid * CH;

    int s = 0;
    for (int i = 0; i < CH; i++) {
        const int idx = start + i;
        if (idx < N_NODES) s += cnt[idx];
    }
    int v = s;
#pragma unroll
    for (int d = 1; d < 32; d <<= 1) {
        int n = __shfl_up_sync(0xffffffffu, v, d);
        if (lane >= d) v += n;
    }
    if (lane == 31) wsum[wid] = v;
    __syncthreads();
    if (wid == 0) {
        int wv = wsum[lane];
#pragma unroll
        for (int d = 1; d < 32; d <<= 1) {
            int n = __shfl_up_sync(0xffffffffu, wv, d);
            if (lane >= d) wv += n;
        }
        wsum[lane] = wv;
    }
    __syncthreads();
    int run = v - s + (wid > 0 ? wsum[wid - 1] : 0);
    for (int i = 0; i < CH; i++) {
        const int idx = start + i;
        if (idx < N_NODES) { base[idx] = run; run += cnt[idx]; }
    }
    if (tid == 1023) base[N_NODES] = run;
}

// ---------------- convert: CSR slot assignment + permutation arrays ----------
__global__ __launch_bounds__(256)
void convert_kernel(const void* __restrict__ eidx,
                    const int* __restrict__ base, int* __restrict__ cnt,
                    int* __restrict__ psrc, int* __restrict__ pdst,
                    int* __restrict__ pinv) {
    const int i = blockIdx.x * blockDim.x + threadIdx.x;
    if (i >= N_EDGES) return;
    int s, d;
    if (g_idx64) {
        const long long* p = (const long long*)eidx;
        s = (int)p[i];
        d = (int)p[(size_t)N_EDGES + i];
    } else {
        const int* p = (const int*)eidx;
        s = p[i];
        d = p[N_EDGES + i];
    }
    const int pp = base[d] + atomicAdd(&cnt[d], 1);
    psrc[pp] = s;
    pdst[pp] = d;
    pinv[pp] = i;
}

// ---------------- node projections: 3 GEMMs in one launch (gridDim.y) ---------
#define BM 64
#define BK 16

__global__ __launch_bounds__(256)
void sgemm3_kernel(const float* __restrict__ A,
                   const float* __restrict__ WQ, const float* __restrict__ WK,
                   const float* __restrict__ WV,
                   float* __restrict__ Q, float* __restrict__ K,
                   float* __restrict__ V, int M) {
    const float* W = (blockIdx.y == 0) ? WQ : (blockIdx.y == 1) ? WK : WV;
    float*       C = (blockIdx.y == 0) ? Q  : (blockIdx.y == 1) ? K  : V;

    __shared__ float As[BK][BM + 1];
    __shared__ float Ws[BK][DIM];

    const int tid = threadIdx.x;
    const int tx = tid & 31;
    const int ty = tid >> 5;
    const int m0 = blockIdx.x * BM;

    float acc[8][4];
#pragma unroll
    for (int i = 0; i < 8; i++)
#pragma unroll
        for (int j = 0; j < 4; j++) acc[i][j] = 0.0f;

    for (int k0 = 0; k0 < DIM; k0 += BK) {
        {
            const int r = tid >> 2;
            const int c = (tid & 3) * 4;
            const int gr = m0 + r;
            float4 a = make_float4(0.f, 0.f, 0.f, 0.f);
            if (gr < M) a = *(const float4*)(A + (size_t)gr * DIM + k0 + c);
            As[c + 0][r] = a.x;
            As[c + 1][r] = a.y;
            As[c + 2][r] = a.z;
            As[c + 3][r] = a.w;
        }
        {
            const int cw = (tid & 31) * 4;
            const int rw = tid >> 5;
            *(float4*)&Ws[rw][cw]     = *(const float4*)(W + (size_t)(k0 + rw) * DIM + cw);
            *(float4*)&Ws[rw + 8][cw] = *(const float4*)(W + (size_t)(k0 + rw + 8) * DIM + cw);
        }
        __syncthreads();

#pragma unroll
        for (int kk = 0; kk < BK; kk++) {
            float a[8];
#pragma unroll
            for (int i = 0; i < 8; i++) a[i] = As[kk][ty * 8 + i];
            const float4 wv = *(const float4*)&Ws[kk][tx * 4];
#pragma unroll
            for (int i = 0; i < 8; i++) {
                acc[i][0] = fmaf(a[i], wv.x, acc[i][0]);
                acc[i][1] = fmaf(a[i], wv.y, acc[i][1]);
                acc[i][2] = fmaf(a[i], wv.z, acc[i][2]);
                acc[i][3] = fmaf(a[i], wv.w, acc[i][3]);
            }
        }
        __syncthreads();
    }

#pragma unroll
    for (int i = 0; i < 8; i++) {
        const int gr = m0 + ty * 8 + i;
        if (gr < M) {
            *(float4*)(C + (size_t)gr * DIM + tx * 4) =
                make_float4(acc[i][0], acc[i][1], acc[i][2], acc[i][3]);
        }
    }
}

// ---------------- tf32 helpers -----------------------------------------------
__device__ __forceinline__ uint32_t f2tf(float f) {
    uint32_t u;
    asm("cvt.rna.tf32.f32 %0, %1;" : "=r"(u) : "f"(f));
    return u;
}

__device__ __forceinline__ void mma_tf32(float* d, const uint32_t* a, const uint32_t* b) {
    asm volatile(
        "mma.sync.aligned.m16n8k8.row.col.f32.tf32.tf32.f32 "
        "{%0,%1,%2,%3}, {%4,%5,%6,%7}, {%8,%9}, {%0,%1,%2,%3};"
        : "+f"(d[0]), "+f"(d[1]), "+f"(d[2]), "+f"(d[3])
        : "r"(a[0]), "r"(a[1]), "r"(a[2]), "r"(a[3]),
          "r"(b[0]), "r"(b[1]));
}

// ---------------- fused edge kernel: persistent, prefetch-pipelined -----------
// Grid = 304 persistent CTAs (2/SM). Each CTA: load WE once as tf32 into SMEM;
// loop over its ~82 tiles of 64 slots: STS prefetched ea rows -> GEMM (while
// prefetching next tile's ea rows into registers) -> Eh to SMEM (aliasing the
// A tile) -> score epilogue (K[src]*Q[dst]*Eh, exp/clip, coalesced pscore).
__global__ __launch_bounds__(256, 2)
void fused_edge_kernel(const float* __restrict__ ea,
                       const float* __restrict__ WE,
                       const float* __restrict__ Q,
                       const float* __restrict__ K,
                       const int* __restrict__ psrc,
                       const int* __restrict__ pdst,
                       const int* __restrict__ pinv,
                       float* __restrict__ pscore) {
    extern __shared__ float smem[];
    uint32_t* Asu = (uint32_t*)smem;                       // 64*PAD (reused as Eh)
    uint32_t* Wsu = (uint32_t*)(smem + TILE_E * PAD);      // 128*PAD

    const int tid  = threadIdx.x;
    const int lane = tid & 31;
    const int w    = tid >> 5;                             // 0..7

    // ---- load WE (128x128) into SMEM as tf32 — ONCE per CTA ----
#pragma unroll
    for (int i = 0; i < 16; i++) {
        const int fidx = tid + 256 * i;        // 0..4095
        const int r  = fidx >> 5;
        const int c4 = (fidx & 31) << 2;
        float4 wv = *(const float4*)(WE + (size_t)r * DIM + c4);
        *(uint4*)&Wsu[r * PAD + c4] =
            make_uint4(f2tf(wv.x), f2tf(wv.y), f2tf(wv.z), f2tf(wv.w));
    }

    const int cnt = 82 + (blockIdx.x < (NTILES - NPER * 82) ? 1 : 0);

    // ---- register prefetch of one A tile (warp w owns rows w, w+8, .., w+56)
    float4 areg[8];
    auto prefetchA = [&](int tile) {
        const int e0 = tile * TILE_E;
        int myp = 0;
        if (lane < 8) myp = __ldg(pinv + e0 + w + 8 * lane);
#pragma unroll
        for (int i = 0; i < 8; i++) {
            const int eid = __shfl_sync(0xffffffffu, myp, i);
            areg[i] = __ldg((const float4*)(ea + (size_t)eid * DIM) + lane);
        }
    };

    prefetchA(blockIdx.x);   // prologue

    const int g  = lane >> 2;
    const int cc = lane & 3;
    const int mb = (w & 1) * 32;
    const int nb = (w >> 1) * 32;

    for (int j = 0; j < cnt; j++) {
        const int tile = blockIdx.x + j * NPER;
        const int e0   = tile * TILE_E;

        __syncthreads();   // previous epilogue done reading Eh (alias of Asu)

        // ---- STS prefetched rows (cvt to tf32) ----
#pragma unroll
        for (int i = 0; i < 8; i++) {
            const int r = w + 8 * i;
            *(uint4*)&Asu[r * PAD + lane * 4] =
                make_uint4(f2tf(areg[i].x), f2tf(areg[i].y),
                           f2tf(areg[i].z), f2tf(areg[i].w));
        }
        __syncthreads();

        // ---- prefetch next tile's A rows (LDGs hide under the GEMM below) ----
        if (j + 1 < cnt) prefetchA(blockIdx.x + (j + 1) * NPER);

        // ---- GEMM: 8 warps, each 32 slots x 32 cols ----
        float acc[2][4][4];
#pragma unroll
        for (int mt = 0; mt < 2; mt++)
#pragma unroll
            for (int nt = 0; nt < 4; nt++)
#pragma unroll
                for (int q = 0; q < 4; q++) acc[mt][nt][q] = 0.0f;

#pragma unroll
        for (int ks = 0; ks < 16; ks++) {
            const int kc = 8 * ks + cc;
            uint32_t a[2][4];
#pragma unroll
            for (int mt = 0; mt < 2; mt++) {
                const int r = mb + 16 * mt + g;
                a[mt][0] = Asu[r * PAD + kc];
                a[mt][1] = Asu[(r + 8) * PAD + kc];
                a[mt][2] = Asu[r * PAD + kc + 4];
                a[mt][3] = Asu[(r + 8) * PAD + kc + 4];
            }
            uint32_t b[4][2];
#pragma unroll
            for (int nt = 0; nt < 4; nt++) {
                const int n = nb + 8 * nt + g;
                b[nt][0] = Wsu[kc * PAD + n];
                b[nt][1] = Wsu[(kc + 4) * PAD + n];
            }
#pragma unroll
            for (int mt = 0; mt < 2; mt++)
#pragma unroll
                for (int nt = 0; nt < 4; nt++)
                    mma_tf32(acc[mt][nt], a[mt], b[nt]);
        }
        __syncthreads();   // everyone done READING Asu

        // ---- write Eh tile over the A tile ----
        float* Eh = smem;   // alias of Asu
#pragma unroll
        for (int mt = 0; mt < 2; mt++) {
#pragma unroll
            for (int nt = 0; nt < 4; nt++) {
                const int r   = mb + 16 * mt + g;
                const int col = nb + 8 * nt + 2 * cc;
                *(float2*)&Eh[r * PAD + col] =
                    make_float2(acc[mt][nt][0], acc[mt][nt][1]);
                *(float2*)&Eh[(r + 8) * PAD + col] =
                    make_float2(acc[mt][nt][2], acc[mt][nt][3]);
            }
        }
        __syncthreads();

        // ---- score + sequential slot write: warp w handles slots 8w..8w+7 ----
#pragma unroll 1
        for (int b0 = 0; b0 < 8; b0 += 4) {
            int src[4];
            float4 ehv[4], kv[4], qv[4];
#pragma unroll
            for (int jj = 0; jj < 4; jj++) {
                const int el   = w * 8 + b0 + jj;
                const int slot = e0 + el;
                src[jj] = __ldg(psrc + slot);
                const int dst = __ldg(pdst + slot);
                ehv[jj] = *(const float4*)&Eh[el * PAD + 4 * lane];
                kv[jj]  = __ldg((const float4*)(K + (size_t)src[jj] * DIM) + lane);
                qv[jj]  = __ldg((const float4*)(Q + (size_t)dst * DIM) + lane);
            }
#pragma unroll
            for (int jj = 0; jj < 4; jj++) {
                float s = ehv[jj].x * kv[jj].x * qv[jj].x +
                          ehv[jj].y * kv[jj].y * qv[jj].y +
                          ehv[jj].z * kv[jj].z * qv[jj].z +
                          ehv[jj].w * kv[jj].w * qv[jj].w;
                s += __shfl_xor_sync(0xffffffffu, s, 1);
                s += __shfl_xor_sync(0xffffffffu, s, 2);
                s *= 0.25f;
                s = expf(fminf(fmaxf(s, -5.0f), 5.0f));
                if ((lane & 3) == 0)
                    pscore[(size_t)(e0 + w * 8 + b0 + jj) * NH + (lane >> 2)] = s;
            }
        }
    }
}

// ---------------- gather: one warp per node, register accumulation ------------
__global__ __launch_bounds__(256)
void gather_kernel(const int* __restrict__ base,
                   const int* __restrict__ psrc,
                   const float* __restrict__ pscore,
                   const float* __restrict__ V,
                   float* __restrict__ out) {
    const int node = (blockIdx.x * blockDim.x + threadIdx.x) >> 5;
    const int lane = threadIdx.x & 31;
    if (node >= N_NODES) return;

    const int b = base[node];
    const int e = base[node + 1];
    const int h = lane >> 2;

    float4 acc = make_float4(0.f, 0.f, 0.f, 0.f);
    float z = 0.f;

    for (int cb = b; cb < e; cb += 32) {
        const int n = min(32, e - cb);
        int mysrc = 0;
        if (cb + lane < e) mysrc = __ldg(psrc + cb + lane);

        int i = 0;
        for (; i + 8 <= n; i += 8) {
#pragma unroll
            for (int u = 0; u < 8; u++) {
                const int src = __shfl_sync(0xffffffffu, mysrc, i + u);
                const float s = __ldg(pscore + (size_t)(cb + i + u) * NH + h);
                const float4 v = __ldg((const float4*)(V + (size_t)src * DIM) + lane);
                acc.x = fmaf(v.x, s, acc.x);
                acc.y = fmaf(v.y, s, acc.y);
                acc.z = fmaf(v.z, s, acc.z);
                acc.w = fmaf(v.w, s, acc.w);
                z += s;
            }
        }
        for (; i < n; i++) {
            const int src = __shfl_sync(0xffffffffu, mysrc, i);
            const float s = __ldg(pscore + (size_t)(cb + i) * NH + h);
            const float4 v = __ldg((const float4*)(V + (size_t)src * DIM) + lane);
            acc.x = fmaf(v.x, s, acc.x);
            acc.y = fmaf(v.y, s, acc.y);
            acc.z = fmaf(v.z, s, acc.z);
            acc.w = fmaf(v.w, s, acc.w);
            z += s;
        }
    }
    const float inv = 1.0f / (z + 1e-6f);
    *(float4*)(out + (size_t)node * DIM + lane * 4) =
        make_float4(acc.x * inv, acc.y * inv, acc.z * inv, acc.w * inv);
}

// ---------------- launch --------------------------------------------------------
extern "C" void kernel_launch(void* const* d_in, const int* in_sizes, int n_in,
                              void* d_out, int out_size) {
    const float* h   = (const float*)d_in[0];
    const float* ea  = (const float*)d_in[1];
    const float* WQ  = (const float*)d_in[2];
    const float* WK  = (const float*)d_in[3];
    const float* WV  = (const float*)d_in[4];
    const float* WE  = (const float*)d_in[5];
    const void*  eix = d_in[6];
    float* out = (float*)d_out;

    void *qp, *kp, *vp, *cntp, *basep, *psrcp, *pdstp, *pinvp, *pscorep;
    cudaGetSymbolAddress(&qp,      g_Q);
    cudaGetSymbolAddress(&kp,      g_K);
    cudaGetSymbolAddress(&vp,      g_V);
    cudaGetSymbolAddress(&cntp,    g_cnt);
    cudaGetSymbolAddress(&basep,   g_base);
    cudaGetSymbolAddress(&psrcp,   g_psrc);
    cudaGetSymbolAddress(&pdstp,   g_pdst);
    cudaGetSymbolAddress(&pinvp,   g_pinv);
    cudaGetSymbolAddress(&pscorep, g_pscore);

    detect_idx_kernel<<<1, 1>>>(eix);

    // CSR build
    cudaMemsetAsync(cntp, 0, N_NODES * sizeof(int));
    hist_kernel<<<(N_EDGES + 255) / 256, 256>>>(eix, (int*)cntp);
    scan_kernel<<<1, 1024>>>((const int*)cntp, (int*)basep);
    cudaMemsetAsync(cntp, 0, N_NODES * sizeof(int));
    convert_kernel<<<(N_EDGES + 255) / 256, 256>>>(
        eix, (const int*)basep, (int*)cntp,
        (int*)psrcp, (int*)pdstp, (int*)pinvp);

    // node projections (3 GEMMs in one launch)
    dim3 gN((N_NODES + BM - 1) / BM, 3);
    sgemm3_kernel<<<gN, 256>>>(h, WQ, WK, WV, (float*)qp, (float*)kp, (float*)vp,
                               N_NODES);

    // fused persistent edge GEMM + score (2 CTAs/SM, WE loaded once per CTA)
    const int smem_bytes = (TILE_E + 128) * PAD * sizeof(float);   // 101376
    cudaFuncSetAttribute(fused_edge_kernel,
                         cudaFuncAttributeMaxDynamicSharedMemorySize, smem_bytes);
    fused_edge_kernel<<<NPER, 256, smem_bytes>>>(
        ea, WE, (const float*)qp, (const float*)kp,
        (const int*)psrcp, (const int*)pdstp, (const int*)pinvp,
        (float*)pscorep);

    // gather + normalize (one warp per node)
    gather_kernel<<<(N_NODES * 32 + 255) / 256, 256>>>(
        (const int*)basep, (const int*)psrcp, (const float*)pscorep,
        (const float*)vp, out);
}